// round 1
// baseline (speedup 1.0000x reference)
#include <cuda_runtime.h>

// VectorQuantizer on GB300 (sm_103a)
// inputs  : d_in[0] = X [16,1024,256] f32  (N=16384, D=256)
//           d_in[1] = E [8192,256]    f32  (K=8192)
// output  : d_out f32 = [ quantized_sg (N*D) | indices (N) | loss (1) | perplexity (1) ]

#define N_TOK  16384
#define D_DIM  256
#define K_CODE 8192

#define BM 64      // rows per block
#define BN 128     // codes per k-tile
#define BK 16      // D chunk
#define XS_STRIDE (D_DIM + 4)   // 260: keeps float4 smem stores aligned + bank-spread

#define GATHER_BLOCKS (N_TOK / 8)   // 2048 (8 warps/block, 1 row/warp)

__device__ float g_esq[K_CODE];
__device__ int   g_idx[N_TOK];
__device__ int   g_counts[K_CODE];
__device__ float g_blocksum[GATHER_BLOCKS];

// ---------------------------------------------------------------- zero
__global__ void vq_zero_kernel() {
    int t = blockIdx.x * blockDim.x + threadIdx.x;
    if (t < K_CODE) g_counts[t] = 0;
}

// ---------------------------------------------------------------- ||e||^2
__global__ void vq_esq_kernel(const float* __restrict__ E) {
    int gwarp = (blockIdx.x * blockDim.x + threadIdx.x) >> 5;
    int lane  = threadIdx.x & 31;
    if (gwarp >= K_CODE) return;
    const float* row = E + (size_t)gwarp * D_DIM;
    float s = 0.f;
#pragma unroll
    for (int q = 0; q < D_DIM / 32; ++q) {
        float v = row[lane + 32 * q];
        s = fmaf(v, v, s);
    }
#pragma unroll
    for (int o = 16; o; o >>= 1) s += __shfl_xor_sync(0xffffffffu, s, o);
    if (lane == 0) g_esq[gwarp] = s;
}

// ---------------------------------------------------------------- distances + argmin
// score(n,k) = ||e_k||^2 - 2 * <x_n, e_k>   (same argmin as reference distances)
__global__ __launch_bounds__(256, 2)
void vq_argmin_kernel(const float* __restrict__ X, const float* __restrict__ E) {
    extern __shared__ float smem[];
    float* Xs   = smem;                        // [BM][XS_STRIDE]
    float* Bs   = Xs + BM * XS_STRIDE;         // [BK][BN]  (k-major)
    float* sEsq = Bs + BK * BN;                // [BN]

    const int tid = threadIdx.x;
    const int tx  = tid & 15;     // code group (8 codes)
    const int ty  = tid >> 4;     // row group  (4 rows)
    const int rowBase = blockIdx.x * BM;

    // Load resident X tile [64][256] with float4, store padded.
    {
        const float4* Xg = (const float4*)(X + (size_t)rowBase * D_DIM);
#pragma unroll
        for (int it = 0; it < 16; ++it) {
            int i4 = it * 256 + tid;          // 4096 float4s
            int r  = i4 >> 6;                 // /64
            int c4 = i4 & 63;
            float4 v = Xg[i4];
            *(float4*)(Xs + r * XS_STRIDE + c4 * 4) = v;
        }
    }

    float runMin[4];
    int   runIdx[4];
#pragma unroll
    for (int i = 0; i < 4; ++i) { runMin[i] = 3.4e38f; runIdx[i] = 0; }

    for (int kt = 0; kt < K_CODE / BN; ++kt) {
        if (tid < BN) sEsq[tid] = g_esq[kt * BN + tid];

        float acc[4][8];
#pragma unroll
        for (int i = 0; i < 4; ++i)
#pragma unroll
            for (int j = 0; j < 8; ++j) acc[i][j] = 0.f;

        for (int dt = 0; dt < D_DIM / BK; ++dt) {
            __syncthreads();   // protects Bs reuse + sEsq store (and Xs on first pass)
            // Load E chunk [BN][BK] transposed into Bs[BK][BN].
            {
                const float* Eg = E + (size_t)(kt * BN) * D_DIM + dt * BK;
#pragma unroll
                for (int q = 0; q < 2; ++q) {
                    int i4 = q * 256 + tid;   // 512 float4s total
                    int c  = i4 >> 2;         // code 0..127
                    int s4 = i4 & 3;          // which float4 of the 16 d's
                    float4 v = *(const float4*)(Eg + (size_t)c * D_DIM + s4 * 4);
                    Bs[(s4 * 4 + 0) * BN + c] = v.x;
                    Bs[(s4 * 4 + 1) * BN + c] = v.y;
                    Bs[(s4 * 4 + 2) * BN + c] = v.z;
                    Bs[(s4 * 4 + 3) * BN + c] = v.w;
                }
            }
            __syncthreads();

#pragma unroll
            for (int kk = 0; kk < BK; ++kk) {
                float a[4], b[8];
#pragma unroll
                for (int i = 0; i < 4; ++i)
                    a[i] = Xs[(ty * 4 + i) * XS_STRIDE + dt * BK + kk];
                const float4* bv = (const float4*)(Bs + kk * BN + tx * 8);
                float4 b0 = bv[0], b1 = bv[1];
                b[0]=b0.x; b[1]=b0.y; b[2]=b0.z; b[3]=b0.w;
                b[4]=b1.x; b[5]=b1.y; b[6]=b1.z; b[7]=b1.w;
#pragma unroll
                for (int i = 0; i < 4; ++i)
#pragma unroll
                    for (int j = 0; j < 8; ++j)
                        acc[i][j] = fmaf(a[i], b[j], acc[i][j]);
            }
        }

        // Epilogue: running argmin (strict <  => keeps earliest index)
#pragma unroll
        for (int j = 0; j < 8; ++j) {
            float eq  = sEsq[tx * 8 + j];
            int  code = kt * BN + tx * 8 + j;
#pragma unroll
            for (int i = 0; i < 4; ++i) {
                float sc = fmaf(-2.f, acc[i][j], eq);
                if (sc < runMin[i]) { runMin[i] = sc; runIdx[i] = code; }
            }
        }
        __syncthreads();   // before next kt overwrites sEsq
    }

    // Cross-tx reduction per row (16 candidates per row), ties -> smaller index.
    float* sMin = Bs;                       // 64*16 floats
    int*   sIdx = (int*)(Bs + BM * 16);     // 64*16 ints  (fits in Bs region: 2048 floats)
#pragma unroll
    for (int i = 0; i < 4; ++i) {
        sMin[(ty * 4 + i) * 16 + tx] = runMin[i];
        sIdx[(ty * 4 + i) * 16 + tx] = runIdx[i];
    }
    __syncthreads();
    if (tid < BM) {
        float best = sMin[tid * 16];
        int   bi   = sIdx[tid * 16];
#pragma unroll
        for (int t = 1; t < 16; ++t) {
            float v  = sMin[tid * 16 + t];
            int   ix = sIdx[tid * 16 + t];
            if (v < best || (v == best && ix < bi)) { best = v; bi = ix; }
        }
        g_idx[rowBase + tid] = bi;
    }
}

// ---------------------------------------------------------------- gather + loss partials + counts
__global__ void vq_gather_kernel(const float* __restrict__ X, const float* __restrict__ E,
                                 float* __restrict__ outQ, float* __restrict__ outIdx,
                                 int writeExtras) {
    __shared__ float warpSums[8];
    int lwarp = threadIdx.x >> 5;
    int lane  = threadIdx.x & 31;
    int row   = blockIdx.x * 8 + lwarp;   // one row per warp

    int idx = g_idx[row];
    const float4* e4 = (const float4*)(E + (size_t)idx * D_DIM);
    const float4* x4 = (const float4*)(X + (size_t)row * D_DIM);
    float4*       o4 = (float4*)(outQ + (size_t)row * D_DIM);

    float s = 0.f;
#pragma unroll
    for (int q = 0; q < 2; ++q) {
        float4 e = e4[lane + 32 * q];
        float4 x = x4[lane + 32 * q];
        // quantized_sg = x + (e - x), computed exactly like the reference
        float dx = e.x - x.x, dy = e.y - x.y, dz = e.z - x.z, dw = e.w - x.w;
        float4 o;
        o.x = x.x + dx; o.y = x.y + dy; o.z = x.z + dz; o.w = x.w + dw;
        o4[lane + 32 * q] = o;
        s += dx * dx + dy * dy + dz * dz + dw * dw;
    }
#pragma unroll
    for (int o = 16; o; o >>= 1) s += __shfl_xor_sync(0xffffffffu, s, o);
    if (lane == 0) {
        warpSums[lwarp] = s;
        atomicAdd(&g_counts[idx], 1);
        if (writeExtras) outIdx[row] = (float)idx;
    }
    __syncthreads();
    if (threadIdx.x == 0) {
        float bs = 0.f;
#pragma unroll
        for (int w = 0; w < 8; ++w) bs += warpSums[w];
        g_blocksum[blockIdx.x] = bs;   // deterministic partial
    }
}

// ---------------------------------------------------------------- finalize: loss + perplexity
__global__ void vq_finalize_kernel(float* __restrict__ outLoss, float* __restrict__ outPerp) {
    __shared__ float sh[256];
    int tid = threadIdx.x;

    // deterministic sum of squared-error partials
    float ss = 0.f;
    for (int b = tid; b < GATHER_BLOCKS; b += 256) ss += g_blocksum[b];
    sh[tid] = ss;
    __syncthreads();
    for (int o = 128; o; o >>= 1) {
        if (tid < o) sh[tid] += sh[tid + o];
        __syncthreads();
    }
    float sumsq = sh[0];
    __syncthreads();

    // entropy over codeword usage
    const float invN = 1.f / (float)N_TOK;
    float ent = 0.f;
    for (int k = tid; k < K_CODE; k += 256) {
        int c = g_counts[k];
        if (c > 0) {
            float p = (float)c * invN;
            ent += p * logf(p + 1e-10f);
        }
    }
    sh[tid] = ent;
    __syncthreads();
    for (int o = 128; o; o >>= 1) {
        if (tid < o) sh[tid] += sh[tid + o];
        __syncthreads();
    }
    if (tid == 0) {
        // loss = q_latent (==0 numerically) + 0.25 * e_latent
        outLoss[0] = 0.25f * sumsq / (float)(N_TOK * D_DIM);
        outPerp[0] = expf(-sh[0]);
    }
}

// ---------------------------------------------------------------- launcher
extern "C" void kernel_launch(void* const* d_in, const int* in_sizes, int n_in,
                              void* d_out, int out_size) {
    const float* X = (const float*)d_in[0];
    const float* E = (const float*)d_in[1];
    float* out = (float*)d_out;

    float* outQ    = out;
    float* outIdx  = out + (size_t)N_TOK * D_DIM;
    float* outLoss = outIdx + N_TOK;
    float* outPerp = outLoss + 1;
    int writeExtras = (out_size >= N_TOK * D_DIM + N_TOK + 2) ? 1 : 0;

    const int smemBytes = (BM * XS_STRIDE + BK * BN + BN) * (int)sizeof(float);
    cudaFuncSetAttribute(vq_argmin_kernel,
                         cudaFuncAttributeMaxDynamicSharedMemorySize, smemBytes);

    vq_zero_kernel<<<(K_CODE + 255) / 256, 256>>>();
    vq_esq_kernel<<<K_CODE / 8, 256>>>(E);
    vq_argmin_kernel<<<N_TOK / BM, 256, smemBytes>>>(X, E);
    vq_gather_kernel<<<GATHER_BLOCKS, 256>>>(X, E, outQ, outIdx, writeExtras);
    if (writeExtras) vq_finalize_kernel<<<1, 256>>>(outLoss, outPerp);
}